// round 14
// baseline (speedup 1.0000x reference)
#include <cuda_runtime.h>
#include <cstdint>

// Integrator: y[b,c,n] = cumsum over time axis. 32 rows, T = 2^20.
//
// R14: blocked layout + redundant per-warp lookback.
//   4096 blocks x 8192 elements, 256 thr x 32 CONTIGUOUS elements each.
//   Phase A: 8 streaming LDG.128 (4KB/warp-instr, fully coalesced), 31-FADD
//   thread-local scan, ONE 5-shfl warp scan (chain ~260 cyc vs ~1300 before).
//   ONE barrier; then every warp independently computes block offsets
//   (fixed shfl_xor grouping) and its own lookback -> warps decouple,
//   no warp waits on another's spin. Gen-tagged spine (no init kernel).
//   Lookback: <=127 preds, <=4/lane, MLP-batched, exact-gen (deterministic).

#define THREADS 256
#define WARPS 8
#define VPT 8                           // float4 per thread (32 floats, contiguous)
#define SEG (THREADS * VPT * 4)         // 8192
#define T_LEN 1048576
#define SEGS_PER_ROW (T_LEN / SEG)      // 128 (power of two)
#define NSEG 4096                       // 32 rows * 128

// Spine word: gen (hi 32) | float bits (lo 32). Zero at module load; every
// launch bumps each entry's gen by exactly 1 (sole-writer handshake).
__device__ unsigned long long g_spine[NSEG];

__device__ __forceinline__ void spine_store(unsigned long long* p, unsigned gen, float v) {
    unsigned long long w = ((unsigned long long)gen << 32)
                         | (unsigned long long)__float_as_uint(v);
    asm volatile("st.global.relaxed.gpu.b64 [%0], %1;" :: "l"(p), "l"(w) : "memory");
}

__device__ __forceinline__ unsigned long long spine_poll(const unsigned long long* p) {
    unsigned long long v;
    asm volatile("ld.global.relaxed.gpu.b64 %0, [%1];" : "=l"(v) : "l"(p) : "memory");
    return v;
}

__global__ __launch_bounds__(THREADS, 5)
void integrator_scan_kernel(const float* __restrict__ x, float* __restrict__ y) {
    __shared__ float s_warp[WARPS];    // per-warp totals
    __shared__ unsigned s_gen;         // this launch's generation

    const int bid = blockIdx.x;
    const int seg_in_row = bid & (SEGS_PER_ROW - 1);
    const long long base = (long long)bid * SEG;

    const int t = threadIdx.x;
    const int lane = t & 31;
    const int warp = t >> 5;

    // Hoisted gen read: in flight while the 8 data loads stream in.
    if (t == 0)
        s_gen = (unsigned)(spine_poll(&g_spine[bid]) >> 32) + 1u;

    const float4* xv = reinterpret_cast<const float4*>(x + base);
    float4* yv = reinterpret_cast<float4*>(y + base);

    // ===== Phase A: blocked load (thread t owns 32 contiguous floats) =====
    float4 d[VPT];
    #pragma unroll
    for (int j = 0; j < VPT; j++)
        d[j] = __ldcs(xv + t * VPT + j);

    // thread-local inclusive scan across all 32 values (serial FADD chain)
    float run = 0.0f;
    #pragma unroll
    for (int j = 0; j < VPT; j++) {
        d[j].x += run;
        d[j].y += d[j].x;
        d[j].z += d[j].y;
        d[j].w += d[j].z;
        run = d[j].w;
    }
    const float tot = run;

    // ONE warp scan over per-thread totals
    float incl = tot;
    #pragma unroll
    for (int dd = 1; dd < 32; dd <<= 1) {
        float n = __shfl_up_sync(0xffffffffu, incl, dd);
        if (lane >= dd) incl += n;
    }
    const float lane_excl = incl - tot;
    if (lane == 31) s_warp[warp] = incl;

    __syncthreads();   // the only barrier

    // ===== Every warp independently: block offsets + publish + lookback =====
    // v = warp totals distributed over lanes 0..7 (fixed layout)
    const float v = (lane < WARPS) ? s_warp[lane] : 0.0f;
    const float wv = (lane < warp) ? v : 0.0f;      // totals of warps before mine

    // fixed shfl_xor tree reduces (deterministic grouping)
    float blocktot = v, woff = wv;
    #pragma unroll
    for (int dd = 16; dd; dd >>= 1) {
        blocktot += __shfl_xor_sync(0xffffffffu, blocktot, dd);
        woff     += __shfl_xor_sync(0xffffffffu, woff, dd);
    }

    const unsigned target = s_gen;
    if (t == 0) spine_store(&g_spine[bid], target, blocktot);

    // Redundant per-warp lookback: <=127 preds, <=4/lane, MLP-batched,
    // exact-gen match, fixed grouping -> bitwise deterministic.
    float excl = 0.0f;
    if (seg_in_row > 0) {
        const int rowbase = bid - seg_in_row;
        const int cnt = (seg_in_row > lane) ? ((seg_in_row - lane + 31) >> 5) : 0;
        float v4[4];
        unsigned pend = (cnt > 0) ? ((1u << cnt) - 1u) : 0u;
        while (pend) {
            unsigned long long w4[4];
            #pragma unroll
            for (int i = 0; i < 4; i++)
                if (pend & (1u << i))
                    w4[i] = spine_poll(&g_spine[rowbase + lane + 32 * i]);
            #pragma unroll
            for (int i = 0; i < 4; i++)
                if ((pend & (1u << i)) && (unsigned)(w4[i] >> 32) == target) {
                    v4[i] = __uint_as_float((unsigned)w4[i]);
                    pend &= ~(1u << i);
                }
        }
        float lsum = 0.0f;
        #pragma unroll
        for (int i = 0; i < 4; i++)
            if (i < cnt) lsum += v4[i];
        #pragma unroll
        for (int dd = 16; dd; dd >>= 1)
            lsum += __shfl_xor_sync(0xffffffffu, lsum, dd);
        excl = lsum;
    }

    // ===== Phase B: store (this warp proceeds as soon as ITS polls done) =====
    const float off = excl + woff + lane_excl;

    #pragma unroll
    for (int j = 0; j < VPT; j++) {
        float4 o = d[j];
        o.x += off; o.y += off; o.z += off; o.w += off;
        __stcs(yv + t * VPT + j, o);
    }
}

extern "C" void kernel_launch(void* const* d_in, const int* in_sizes, int n_in,
                              void* d_out, int out_size) {
    const float* x = (const float*)d_in[0];
    float* y = (float*)d_out;

    const int n = out_size;              // 33554432
    const int nseg = n / SEG;            // 4096

    integrator_scan_kernel<<<nseg, THREADS>>>(x, y);
}

// round 15
// speedup vs baseline: 1.6696x; 1.6696x over previous
#include <cuda_runtime.h>
#include <cstdint>

// Integrator: y[b,c,n] = cumsum over time axis. 32 rows, T = 2^20.
//
// R15: R13's winning layout, 2 adjacent tiles per block (16K elems).
//   2048 blocks x 16384 elements; 256 thr x 16 float4 (warp-interleaved
//   per tile -> nL=4 lines/request, coalesced). All 16 loads up front (2x
//   MLP). ONE 16-lane warp-0 scan covers both tiles; tile B's offset comes
//   from the joint scan -> one lookback, one publish step, 2 barriers for
//   2x the data. Gen-tagged spine (no init kernel), hoisted gen read.
//   Lookback: <=126 preds, <=4/lane, MLP-batched, exact-gen, fixed
//   grouping (bitwise deterministic). Phase B: add offset + STG.128 only.

#define THREADS 256
#define WARPS 8
#define VPT 8                            // float4 per thread PER TILE
#define TILE 8192                        // elements per spine tile
#define SEGB (2 * TILE)                  // 16384 elements per block
#define F4_PER_WARP 256                  // float4 per warp per tile
#define F4_TILE 2048                     // float4 per tile
#define T_LEN 1048576
#define TILES_PER_ROW (T_LEN / TILE)     // 128 (power of two)
#define BLOCKS_PER_ROW (TILES_PER_ROW/2) // 64
#define NSEG 4096                        // spine entries: 32 rows * 128 tiles

// Spine word: gen (hi 32) | float bits (lo 32). Zero at module load; every
// launch bumps each entry's gen by exactly 1 (sole-writer handshake), so
// exact-gen matching is replay-safe with no init kernel.
__device__ unsigned long long g_spine[NSEG];

__device__ __forceinline__ void spine_store(unsigned long long* p, unsigned gen, float v) {
    unsigned long long w = ((unsigned long long)gen << 32)
                         | (unsigned long long)__float_as_uint(v);
    asm volatile("st.global.relaxed.gpu.b64 [%0], %1;" :: "l"(p), "l"(w) : "memory");
}

__device__ __forceinline__ unsigned long long spine_poll(const unsigned long long* p) {
    unsigned long long v;
    asm volatile("ld.global.relaxed.gpu.b64 %0, [%1];" : "=l"(v) : "l"(p) : "memory");
    return v;
}

__global__ __launch_bounds__(THREADS, 3)
void integrator_scan_kernel(const float* __restrict__ x, float* __restrict__ y) {
    __shared__ float s_warp[16];       // warp totals: A in [0,8), B in [8,16)
    __shared__ float s_woff[16];       // joint exclusive offsets (B includes totA)
    __shared__ float s_excl;           // exclusive prefix of tile A
    __shared__ unsigned s_gen;         // this launch's generation

    const int bid = blockIdx.x;
    const int rb = bid & (BLOCKS_PER_ROW - 1);     // block index within row
    const long long base = (long long)bid * SEGB;

    const int t = threadIdx.x;
    const int lane = t & 31;
    const int warp = t >> 5;

    // Hoisted gen read: in flight while the 16 data loads stream in.
    if (t == 0)
        s_gen = (unsigned)(spine_poll(&g_spine[2 * bid]) >> 32) + 1u;

    const float4* xv = reinterpret_cast<const float4*>(x + base);
    float4* yv = reinterpret_cast<float4*>(y + base);

    // ===== Phase A: both tiles loaded up front (16 outstanding LDG.128) ====
    float4 d0[VPT], d1[VPT];
    #pragma unroll
    for (int j = 0; j < VPT; j++)
        d0[j] = __ldcs(xv + warp * F4_PER_WARP + j * 32 + lane);
    #pragma unroll
    for (int j = 0; j < VPT; j++)
        d1[j] = __ldcs(xv + F4_TILE + warp * F4_PER_WARP + j * 32 + lane);

    // warp-span scan folded into registers, tile A
    float carryA = 0.0f;
    #pragma unroll
    for (int j = 0; j < VPT; j++) {
        d0[j].y += d0[j].x; d0[j].z += d0[j].y; d0[j].w += d0[j].z;
        const float tot = d0[j].w;
        float incl = tot;
        #pragma unroll
        for (int dd = 1; dd < 32; dd <<= 1) {
            float n = __shfl_up_sync(0xffffffffu, incl, dd);
            if (lane >= dd) incl += n;
        }
        const float add = carryA + (incl - tot);
        d0[j].x += add; d0[j].y += add; d0[j].z += add; d0[j].w += add;
        carryA += __shfl_sync(0xffffffffu, incl, 31);
    }
    // tile B
    float carryB = 0.0f;
    #pragma unroll
    for (int j = 0; j < VPT; j++) {
        d1[j].y += d1[j].x; d1[j].z += d1[j].y; d1[j].w += d1[j].z;
        const float tot = d1[j].w;
        float incl = tot;
        #pragma unroll
        for (int dd = 1; dd < 32; dd <<= 1) {
            float n = __shfl_up_sync(0xffffffffu, incl, dd);
            if (lane >= dd) incl += n;
        }
        const float add = carryB + (incl - tot);
        d1[j].x += add; d1[j].y += add; d1[j].z += add; d1[j].w += add;
        carryB += __shfl_sync(0xffffffffu, incl, 31);
    }
    if (lane == 0) {
        s_warp[warp] = carryA;
        s_warp[8 + warp] = carryB;
    }

    __syncthreads();

    if (warp == 0) {
        // joint 16-lane scan: lanes 0..7 = tile A warps, 8..15 = tile B warps
        const float v = (lane < 16) ? s_warp[lane] : 0.0f;
        float incl = v;
        #pragma unroll
        for (int dd = 1; dd < 16; dd <<= 1) {
            float n = __shfl_up_sync(0xffffffffu, incl, dd);
            if (lane >= dd) incl += n;
        }
        if (lane < 16) s_woff[lane] = incl - v;
        const float totA   = __shfl_sync(0xffffffffu, incl, 7);
        const float totAll = __shfl_sync(0xffffffffu, incl, 15);

        const unsigned target = s_gen;          // read overlapped the loads
        if (lane == 0) spine_store(&g_spine[2 * bid],     target, totA);
        if (lane == 1) spine_store(&g_spine[2 * bid + 1], target, totAll - totA);

        // Deterministic lookback for tile A: <=126 preds, <=4/lane,
        // MLP-batched polling, exact-gen match, fixed grouping.
        float excl = 0.0f;
        const int tir = 2 * rb;                 // tile A's index within row
        if (tir > 0) {
            const int rowbase = 2 * bid - tir;  // first tile of this row
            const int cnt = (tir > lane) ? ((tir - lane + 31) >> 5) : 0;
            float v4[4];
            unsigned pend = (cnt > 0) ? ((1u << cnt) - 1u) : 0u;
            while (pend) {
                unsigned long long w4[4];
                #pragma unroll
                for (int i = 0; i < 4; i++)
                    if (pend & (1u << i))
                        w4[i] = spine_poll(&g_spine[rowbase + lane + 32 * i]);
                #pragma unroll
                for (int i = 0; i < 4; i++)
                    if ((pend & (1u << i)) && (unsigned)(w4[i] >> 32) == target) {
                        v4[i] = __uint_as_float((unsigned)w4[i]);
                        pend &= ~(1u << i);
                    }
            }
            float lsum = 0.0f;
            #pragma unroll
            for (int i = 0; i < 4; i++)
                if (i < cnt) lsum += v4[i];
            #pragma unroll
            for (int dd = 16; dd; dd >>= 1)
                lsum += __shfl_xor_sync(0xffffffffu, lsum, dd);
            excl = lsum;
        }
        if (lane == 0) s_excl = excl;
    }

    __syncthreads();

    // ===== Phase B: registers -> global. No loads, no shfls, no barriers. ====
    const float offA = s_excl + s_woff[warp];
    const float offB = s_excl + s_woff[8 + warp];   // joint scan includes totA

    #pragma unroll
    for (int j = 0; j < VPT; j++) {
        float4 o = d0[j];
        o.x += offA; o.y += offA; o.z += offA; o.w += offA;
        __stcs(yv + warp * F4_PER_WARP + j * 32 + lane, o);
    }
    #pragma unroll
    for (int j = 0; j < VPT; j++) {
        float4 o = d1[j];
        o.x += offB; o.y += offB; o.z += offB; o.w += offB;
        __stcs(yv + F4_TILE + warp * F4_PER_WARP + j * 32 + lane, o);
    }
}

extern "C" void kernel_launch(void* const* d_in, const int* in_sizes, int n_in,
                              void* d_out, int out_size) {
    const float* x = (const float*)d_in[0];
    float* y = (float*)d_out;

    const int n = out_size;              // 33554432
    const int nblocks = n / SEGB;        // 2048

    integrator_scan_kernel<<<nblocks, THREADS>>>(x, y);
}

// round 16
// speedup vs baseline: 1.7395x; 1.0419x over previous
#include <cuda_runtime.h>
#include <cstdint>

// Integrator: y[b,c,n] = cumsum over time axis. 32 rows, T = 2^20.
//
// R16: R15 (2 tiles/block, joint scan, one lookback) + cp.async-staged tile B.
//   Tile A: DRAM -> registers (8 LDG.128/thread). Tile B: DRAM -> smem via
//   cp.async.cg (no registers in flight) -> regs are freed for 4 blocks/SM.
//   In-flight/SM: 4 x (32KB LDG + 32KB LDGSTS) = 256KB (R15: 196KB), occ 50%.
//   Joint 16-lane warp-0 scan covers both tiles; ONE lookback per block.
//   Gen-tagged spine (no init kernel), hoisted gen read, exact-gen match,
//   fixed grouping everywhere -> bitwise deterministic. 2 barriers total.

#define THREADS 256
#define WARPS 8
#define VPT 8                            // float4 per thread per tile
#define TILE 8192                        // elements per spine tile
#define SEGB (2 * TILE)                  // 16384 elements per block
#define F4_PER_WARP 256                  // float4 per warp per tile
#define F4_TILE 2048                     // float4 per tile
#define T_LEN 1048576
#define TILES_PER_ROW (T_LEN / TILE)     // 128 (power of two)
#define BLOCKS_PER_ROW (TILES_PER_ROW/2) // 64
#define NSEG 4096                        // spine entries: 32 rows * 128 tiles

// Spine word: gen (hi 32) | float bits (lo 32). Zero at module load; every
// launch bumps each entry's gen by exactly 1 (sole-writer handshake).
__device__ unsigned long long g_spine[NSEG];

__device__ __forceinline__ void spine_store(unsigned long long* p, unsigned gen, float v) {
    unsigned long long w = ((unsigned long long)gen << 32)
                         | (unsigned long long)__float_as_uint(v);
    asm volatile("st.global.relaxed.gpu.b64 [%0], %1;" :: "l"(p), "l"(w) : "memory");
}

__device__ __forceinline__ unsigned long long spine_poll(const unsigned long long* p) {
    unsigned long long v;
    asm volatile("ld.global.relaxed.gpu.b64 %0, [%1];" : "=l"(v) : "l"(p) : "memory");
    return v;
}

__device__ __forceinline__ void cp_async16(void* smem_dst, const void* gmem_src) {
    unsigned saddr = (unsigned)__cvta_generic_to_shared(smem_dst);
    asm volatile("cp.async.cg.shared.global [%0], [%1], 16;" :: "r"(saddr), "l"(gmem_src));
}

__global__ __launch_bounds__(THREADS, 4)
void integrator_scan_kernel(const float* __restrict__ x, float* __restrict__ y) {
    __shared__ float4 s_b[F4_TILE];    // tile B staging (32 KB)
    __shared__ float s_warp[16];       // warp totals: A in [0,8), B in [8,16)
    __shared__ float s_woff[16];       // joint exclusive offsets
    __shared__ float s_excl;           // exclusive prefix of tile A
    __shared__ unsigned s_gen;         // this launch's generation

    const int bid = blockIdx.x;
    const int rb = bid & (BLOCKS_PER_ROW - 1);
    const long long base = (long long)bid * SEGB;

    const int t = threadIdx.x;
    const int lane = t & 31;
    const int warp = t >> 5;

    // Hoisted gen read: in flight while phase-A loads stream in.
    if (t == 0)
        s_gen = (unsigned)(spine_poll(&g_spine[2 * bid]) >> 32) + 1u;

    const float4* xv = reinterpret_cast<const float4*>(x + base);
    float4* yv = reinterpret_cast<float4*>(y + base);
    const int myf4 = warp * F4_PER_WARP + lane;   // + j*32

    // ===== Phase A: tile A -> registers, tile B -> smem (cp.async) =====
    float4 d[VPT];
    #pragma unroll
    for (int j = 0; j < VPT; j++)
        d[j] = __ldcs(xv + myf4 + j * 32);

    #pragma unroll
    for (int j = 0; j < VPT; j++)
        cp_async16(&s_b[myf4 + j * 32], xv + F4_TILE + myf4 + j * 32);
    asm volatile("cp.async.commit_group;" ::: "memory");

    // scan tile A in registers (warp-span prefix folded in)
    float carryA = 0.0f;
    #pragma unroll
    for (int j = 0; j < VPT; j++) {
        d[j].y += d[j].x; d[j].z += d[j].y; d[j].w += d[j].z;
        const float tot = d[j].w;
        float incl = tot;
        #pragma unroll
        for (int dd = 1; dd < 32; dd <<= 1) {
            float n = __shfl_up_sync(0xffffffffu, incl, dd);
            if (lane >= dd) incl += n;
        }
        const float add = carryA + (incl - tot);
        d[j].x += add; d[j].y += add; d[j].z += add; d[j].w += add;
        carryA += __shfl_sync(0xffffffffu, incl, 31);
    }
    if (lane == 0) s_warp[warp] = carryA;

    // tile B arrived in smem: quick lane-sum pass (each thread reads only
    // the bytes IT copied -> wait_group alone is sufficient, no barrier).
    asm volatile("cp.async.wait_group 0;" ::: "memory");
    float sB = 0.0f;
    #pragma unroll
    for (int j = 0; j < VPT; j++) {
        const float4 v = s_b[myf4 + j * 32];
        sB += (v.x + v.y) + (v.z + v.w);
    }
    // fixed shfl_xor grouping -> deterministic warp total for tile B
    #pragma unroll
    for (int dd = 16; dd; dd >>= 1)
        sB += __shfl_xor_sync(0xffffffffu, sB, dd);
    if (lane == 0) s_warp[8 + warp] = sB;

    __syncthreads();

    if (warp == 0) {
        // joint 16-lane scan: lanes 0..7 = tile A warps, 8..15 = tile B warps
        const float v = (lane < 16) ? s_warp[lane] : 0.0f;
        float incl = v;
        #pragma unroll
        for (int dd = 1; dd < 16; dd <<= 1) {
            float n = __shfl_up_sync(0xffffffffu, incl, dd);
            if (lane >= dd) incl += n;
        }
        if (lane < 16) s_woff[lane] = incl - v;
        const float totA   = __shfl_sync(0xffffffffu, incl, 7);
        const float totAll = __shfl_sync(0xffffffffu, incl, 15);

        const unsigned target = s_gen;
        if (lane == 0) spine_store(&g_spine[2 * bid],     target, totA);
        if (lane == 1) spine_store(&g_spine[2 * bid + 1], target, totAll - totA);

        // Deterministic lookback for tile A: <=126 preds, <=4/lane,
        // MLP-batched polling, exact-gen match, fixed grouping.
        float excl = 0.0f;
        const int tir = 2 * rb;
        if (tir > 0) {
            const int rowbase = 2 * bid - tir;
            const int cnt = (tir > lane) ? ((tir - lane + 31) >> 5) : 0;
            float v4[4];
            unsigned pend = (cnt > 0) ? ((1u << cnt) - 1u) : 0u;
            while (pend) {
                unsigned long long w4[4];
                #pragma unroll
                for (int i = 0; i < 4; i++)
                    if (pend & (1u << i))
                        w4[i] = spine_poll(&g_spine[rowbase + lane + 32 * i]);
                #pragma unroll
                for (int i = 0; i < 4; i++)
                    if ((pend & (1u << i)) && (unsigned)(w4[i] >> 32) == target) {
                        v4[i] = __uint_as_float((unsigned)w4[i]);
                        pend &= ~(1u << i);
                    }
            }
            float lsum = 0.0f;
            #pragma unroll
            for (int i = 0; i < 4; i++)
                if (i < cnt) lsum += v4[i];
            #pragma unroll
            for (int dd = 16; dd; dd >>= 1)
                lsum += __shfl_xor_sync(0xffffffffu, lsum, dd);
            excl = lsum;
        }
        if (lane == 0) s_excl = excl;
    }

    __syncthreads();

    // ===== Phase B: store tile A, then scan+store tile B (regs reused) =====
    const float offA = s_excl + s_woff[warp];
    #pragma unroll
    for (int j = 0; j < VPT; j++) {
        float4 o = d[j];
        o.x += offA; o.y += offA; o.z += offA; o.w += offA;
        __stcs(yv + myf4 + j * 32, o);
    }

    // tile B: re-read own smem region (own data, no barrier), scan, store.
    float carryB = s_excl + s_woff[8 + warp];
    #pragma unroll
    for (int j = 0; j < VPT; j++) {
        float4 o = s_b[myf4 + j * 32];
        o.y += o.x; o.z += o.y; o.w += o.z;
        const float tot = o.w;
        float incl = tot;
        #pragma unroll
        for (int dd = 1; dd < 32; dd <<= 1) {
            float n = __shfl_up_sync(0xffffffffu, incl, dd);
            if (lane >= dd) incl += n;
        }
        const float add = carryB + (incl - tot);
        o.x += add; o.y += add; o.z += add; o.w += add;
        __stcs(yv + F4_TILE + myf4 + j * 32, o);
        carryB += __shfl_sync(0xffffffffu, incl, 31);
    }
}

extern "C" void kernel_launch(void* const* d_in, const int* in_sizes, int n_in,
                              void* d_out, int out_size) {
    const float* x = (const float*)d_in[0];
    float* y = (float*)d_out;

    const int n = out_size;              // 33554432
    const int nblocks = n / SEGB;        // 2048

    integrator_scan_kernel<<<nblocks, THREADS>>>(x, y);
}

// round 17
// speedup vs baseline: 1.7526x; 1.0075x over previous
#include <cuda_runtime.h>
#include <cstdint>

// Integrator: y[b,c,n] = cumsum over time axis. 32 rows, T = 2^20.
//
// R17: R16 + publish-ASAP (tile A's scan deferred past the lookback).
//   2048 blocks x 16384 elems. Tile A -> regs (8 LDG.128/thr), tile B ->
//   smem via cp.async.cg. Phase A now computes ONLY sums for both tiles
//   (8 FADDs + one shfl_xor reduce each, ~200 cyc) before publishing the
//   two spine aggregates -> successors' spins shorten by ~1100 cyc/block.
//   All full scans (fold + store) run post-lookback where other resident
//   blocks hide them. Gen-tagged spine (no init kernel), hoisted gen read,
//   exact-gen MLP-batched lookback, fixed grouping -> bitwise deterministic.

#define THREADS 256
#define WARPS 8
#define VPT 8                            // float4 per thread per tile
#define TILE 8192                        // elements per spine tile
#define SEGB (2 * TILE)                  // 16384 elements per block
#define F4_PER_WARP 256                  // float4 per warp per tile
#define F4_TILE 2048                     // float4 per tile
#define T_LEN 1048576
#define TILES_PER_ROW (T_LEN / TILE)     // 128 (power of two)
#define BLOCKS_PER_ROW (TILES_PER_ROW/2) // 64
#define NSEG 4096                        // spine entries: 32 rows * 128 tiles

// Spine word: gen (hi 32) | float bits (lo 32). Zero at module load; every
// launch bumps each entry's gen by exactly 1 (sole-writer handshake).
__device__ unsigned long long g_spine[NSEG];

__device__ __forceinline__ void spine_store(unsigned long long* p, unsigned gen, float v) {
    unsigned long long w = ((unsigned long long)gen << 32)
                         | (unsigned long long)__float_as_uint(v);
    asm volatile("st.global.relaxed.gpu.b64 [%0], %1;" :: "l"(p), "l"(w) : "memory");
}

__device__ __forceinline__ unsigned long long spine_poll(const unsigned long long* p) {
    unsigned long long v;
    asm volatile("ld.global.relaxed.gpu.b64 %0, [%1];" : "=l"(v) : "l"(p) : "memory");
    return v;
}

__device__ __forceinline__ void cp_async16(void* smem_dst, const void* gmem_src) {
    unsigned saddr = (unsigned)__cvta_generic_to_shared(smem_dst);
    asm volatile("cp.async.cg.shared.global [%0], [%1], 16;" :: "r"(saddr), "l"(gmem_src));
}

__global__ __launch_bounds__(THREADS, 4)
void integrator_scan_kernel(const float* __restrict__ x, float* __restrict__ y) {
    __shared__ float4 s_b[F4_TILE];    // tile B staging (32 KB)
    __shared__ float s_warp[16];       // warp totals: A in [0,8), B in [8,16)
    __shared__ float s_woff[16];       // joint exclusive offsets
    __shared__ float s_excl;           // exclusive prefix of tile A
    __shared__ unsigned s_gen;         // this launch's generation

    const int bid = blockIdx.x;
    const int rb = bid & (BLOCKS_PER_ROW - 1);
    const long long base = (long long)bid * SEGB;

    const int t = threadIdx.x;
    const int lane = t & 31;
    const int warp = t >> 5;

    // Hoisted gen read: in flight while phase-A loads stream in.
    if (t == 0)
        s_gen = (unsigned)(spine_poll(&g_spine[2 * bid]) >> 32) + 1u;

    const float4* xv = reinterpret_cast<const float4*>(x + base);
    float4* yv = reinterpret_cast<float4*>(y + base);
    const int myf4 = warp * F4_PER_WARP + lane;   // + j*32

    // ===== Phase A: tile A -> registers, tile B -> smem (cp.async) =====
    float4 d[VPT];
    #pragma unroll
    for (int j = 0; j < VPT; j++)
        d[j] = __ldcs(xv + myf4 + j * 32);

    #pragma unroll
    for (int j = 0; j < VPT; j++)
        cp_async16(&s_b[myf4 + j * 32], xv + F4_TILE + myf4 + j * 32);
    asm volatile("cp.async.commit_group;" ::: "memory");

    // Tile A: SUM ONLY (publish-ASAP; full scan deferred to phase B).
    float sA = 0.0f;
    #pragma unroll
    for (int j = 0; j < VPT; j++)
        sA += (d[j].x + d[j].y) + (d[j].z + d[j].w);
    #pragma unroll
    for (int dd = 16; dd; dd >>= 1)
        sA += __shfl_xor_sync(0xffffffffu, sA, dd);
    if (lane == 0) s_warp[warp] = sA;

    // Tile B arrived in smem: sum only (each thread reads only bytes IT
    // copied -> wait_group alone is sufficient, no barrier).
    asm volatile("cp.async.wait_group 0;" ::: "memory");
    float sB = 0.0f;
    #pragma unroll
    for (int j = 0; j < VPT; j++) {
        const float4 v = s_b[myf4 + j * 32];
        sB += (v.x + v.y) + (v.z + v.w);
    }
    #pragma unroll
    for (int dd = 16; dd; dd >>= 1)
        sB += __shfl_xor_sync(0xffffffffu, sB, dd);
    if (lane == 0) s_warp[8 + warp] = sB;

    __syncthreads();

    if (warp == 0) {
        // joint 16-lane scan: lanes 0..7 = tile A warps, 8..15 = tile B warps
        const float v = (lane < 16) ? s_warp[lane] : 0.0f;
        float incl = v;
        #pragma unroll
        for (int dd = 1; dd < 16; dd <<= 1) {
            float n = __shfl_up_sync(0xffffffffu, incl, dd);
            if (lane >= dd) incl += n;
        }
        if (lane < 16) s_woff[lane] = incl - v;
        const float totA   = __shfl_sync(0xffffffffu, incl, 7);
        const float totAll = __shfl_sync(0xffffffffu, incl, 15);

        const unsigned target = s_gen;
        if (lane == 0) spine_store(&g_spine[2 * bid],     target, totA);
        if (lane == 1) spine_store(&g_spine[2 * bid + 1], target, totAll - totA);

        // Deterministic lookback for tile A: <=126 preds, <=4/lane,
        // MLP-batched polling, exact-gen match, fixed grouping.
        float excl = 0.0f;
        const int tir = 2 * rb;
        if (tir > 0) {
            const int rowbase = 2 * bid - tir;
            const int cnt = (tir > lane) ? ((tir - lane + 31) >> 5) : 0;
            float v4[4];
            unsigned pend = (cnt > 0) ? ((1u << cnt) - 1u) : 0u;
            while (pend) {
                unsigned long long w4[4];
                #pragma unroll
                for (int i = 0; i < 4; i++)
                    if (pend & (1u << i))
                        w4[i] = spine_poll(&g_spine[rowbase + lane + 32 * i]);
                #pragma unroll
                for (int i = 0; i < 4; i++)
                    if ((pend & (1u << i)) && (unsigned)(w4[i] >> 32) == target) {
                        v4[i] = __uint_as_float((unsigned)w4[i]);
                        pend &= ~(1u << i);
                    }
            }
            float lsum = 0.0f;
            #pragma unroll
            for (int i = 0; i < 4; i++)
                if (i < cnt) lsum += v4[i];
            #pragma unroll
            for (int dd = 16; dd; dd >>= 1)
                lsum += __shfl_xor_sync(0xffffffffu, lsum, dd);
            excl = lsum;
        }
        if (lane == 0) s_excl = excl;
    }

    __syncthreads();

    // ===== Phase B: full scans + stores (off the publish critical path) ====
    // Tile A from registers.
    float carryA = s_excl + s_woff[warp];
    #pragma unroll
    for (int j = 0; j < VPT; j++) {
        float4 o = d[j];
        o.y += o.x; o.z += o.y; o.w += o.z;
        const float tot = o.w;
        float incl = tot;
        #pragma unroll
        for (int dd = 1; dd < 32; dd <<= 1) {
            float n = __shfl_up_sync(0xffffffffu, incl, dd);
            if (lane >= dd) incl += n;
        }
        const float add = carryA + (incl - tot);
        o.x += add; o.y += add; o.z += add; o.w += add;
        __stcs(yv + myf4 + j * 32, o);
        carryA += __shfl_sync(0xffffffffu, incl, 31);
    }

    // Tile B from smem (own region -> no barrier needed).
    float carryB = s_excl + s_woff[8 + warp];
    #pragma unroll
    for (int j = 0; j < VPT; j++) {
        float4 o = s_b[myf4 + j * 32];
        o.y += o.x; o.z += o.y; o.w += o.z;
        const float tot = o.w;
        float incl = tot;
        #pragma unroll
        for (int dd = 1; dd < 32; dd <<= 1) {
            float n = __shfl_up_sync(0xffffffffu, incl, dd);
            if (lane >= dd) incl += n;
        }
        const float add = carryB + (incl - tot);
        o.x += add; o.y += add; o.z += add; o.w += add;
        __stcs(yv + F4_TILE + myf4 + j * 32, o);
        carryB += __shfl_sync(0xffffffffu, incl, 31);
    }
}

extern "C" void kernel_launch(void* const* d_in, const int* in_sizes, int n_in,
                              void* d_out, int out_size) {
    const float* x = (const float*)d_in[0];
    float* y = (float*)d_out;

    const int n = out_size;              // 33554432
    const int nblocks = n / SEGB;        // 2048

    integrator_scan_kernel<<<nblocks, THREADS>>>(x, y);
}